// round 7
// baseline (speedup 1.0000x reference)
#include <cuda_runtime.h>
#include <cuda_bf16.h>
#include <cstdint>

#define N_NODES 100000
#define N_EDGES 1250000
#define D_IN 32
#define H 64
#define EPS 1e-5f

// scratch for hidden features h [N_NODES, H]
__device__ float g_h[(size_t)N_NODES * H];

// packed f32x2 helpers (Blackwell FFMA2 — only reachable via PTX)
__device__ __forceinline__ unsigned long long fma2(unsigned long long a,
                                                   unsigned long long b,
                                                   unsigned long long c)
{
    unsigned long long d;
    asm("fma.rn.f32x2 %0, %1, %2, %3;" : "=l"(d) : "l"(a), "l"(b), "l"(c));
    return d;
}
__device__ __forceinline__ unsigned long long pack2(float v)
{
    unsigned long long d;
    unsigned int u = __float_as_uint(v);
    asm("mov.b64 %0, {%1, %1};" : "=l"(d) : "r"(u));
    return d;
}
__device__ __forceinline__ void unpack2(unsigned long long v, float& lo, float& hi)
{
    unsigned int a, b;
    asm("mov.b64 {%0, %1}, %2;" : "=r"(a), "=r"(b) : "l"(v));
    lo = __uint_as_float(a); hi = __uint_as_float(b);
}

// ---------------------------------------------------------------------------
// MLP: thread = node. Packed f32x2 accumulators, broadcast LDS.128 weights,
// x in conflict-free smem (stride 33). Layer 2 split into two 32-output
// halves so peak live regs ~105 < 128 cap -> no spills at 4 blocks/SM.
// Writes h to g_h AND initializes out = h.
// ---------------------------------------------------------------------------
__global__ __launch_bounds__(128, 4)
void mlp_kernel(const float* __restrict__ x,
                const float* __restrict__ W1, const float* __restrict__ b1,
                const float* __restrict__ g1, const float* __restrict__ be1,
                const float* __restrict__ W2, const float* __restrict__ b2,
                const float* __restrict__ g2, const float* __restrict__ be2,
                float* __restrict__ h_out, float* __restrict__ out)
{
    __shared__ __align__(16) float sW1[D_IN * H];    // 8 KB
    __shared__ __align__(16) float sW2[H * H];       // 16 KB
    __shared__ __align__(16) float sx[128 * 33];     // 16.5 KB x / staging (stride 33)
    __shared__ __align__(16) float sb1[H], sg1[H], sbe1[H], sb2[H], sg2[H], sbe2[H];

    const int tid = threadIdx.x;
    const int B   = blockIdx.x * 128;

    for (int i = tid; i < D_IN * H; i += 128) sW1[i] = W1[i];
    for (int i = tid; i < H * H;    i += 128) sW2[i] = W2[i];
    if (tid < H) {
        sb1[tid] = b1[tid]; sg1[tid] = g1[tid]; sbe1[tid] = be1[tid];
        sb2[tid] = b2[tid]; sg2[tid] = g2[tid]; sbe2[tid] = be2[tid];
    }

    // stage x tile coalesced into smem (stride 33: bank = t + k, conflict-free)
    for (int l = tid; l < 128 * D_IN; l += 128) {
        int n = l >> 5, k = l & 31;
        long long gidx = (long long)B * D_IN + l;
        sx[n * 33 + k] = (gidx < (long long)N_NODES * D_IN) ? x[gidx] : 0.f;
    }
    __syncthreads();

    // ---- layer 1: 32 -> 64  (packed f32x2 accumulators, 64 regs) ----
    float h1[H];
    {
        unsigned long long acc[H / 2];
        #pragma unroll
        for (int j2 = 0; j2 < H / 2; j2++)
            acc[j2] = reinterpret_cast<const unsigned long long*>(sb1)[j2];

        #pragma unroll 8
        for (int k = 0; k < D_IN; k++) {
            unsigned long long xk2 = pack2(sx[tid * 33 + k]);
            const ulonglong2* wrow = reinterpret_cast<const ulonglong2*>(&sW1[k * H]);
            #pragma unroll
            for (int j4 = 0; j4 < 16; j4++) {
                ulonglong2 w = wrow[j4];
                acc[j4*2+0] = fma2(xk2, w.x, acc[j4*2+0]);
                acc[j4*2+1] = fma2(xk2, w.y, acc[j4*2+1]);
            }
        }
        #pragma unroll
        for (int j2 = 0; j2 < H / 2; j2++) unpack2(acc[j2], h1[j2*2], h1[j2*2+1]);
    }
    {   // LN + ReLU (thread-local)
        float s = 0.f, sq = 0.f;
        #pragma unroll
        for (int j = 0; j < H; j++) { s += h1[j]; sq = fmaf(h1[j], h1[j], sq); }
        float mu  = s * (1.f / H);
        float var = sq * (1.f / H) - mu * mu;
        float inv = rsqrtf(var + EPS);
        #pragma unroll
        for (int j = 0; j < H; j++)
            h1[j] = fmaxf(fmaf((h1[j] - mu) * inv, sg1[j], sbe1[j]), 0.f);
    }

    // ---- layer 2: 64 -> 64, two 32-output halves (acc = 32 regs each) ----
    float s2 = 0.f, sq2 = 0.f;

    // half A: j = 0..31 -> pre-LN values staged to own sx row (x is dead)
    {
        unsigned long long acc[16];
        #pragma unroll
        for (int j2 = 0; j2 < 16; j2++)
            acc[j2] = reinterpret_cast<const unsigned long long*>(sb2)[j2];

        #pragma unroll 8
        for (int k = 0; k < H; k++) {
            unsigned long long hk2 = pack2(h1[k]);
            const ulonglong2* wrow = reinterpret_cast<const ulonglong2*>(&sW2[k * H]);
            #pragma unroll
            for (int j4 = 0; j4 < 8; j4++) {
                ulonglong2 w = wrow[j4];
                acc[j4*2+0] = fma2(hk2, w.x, acc[j4*2+0]);
                acc[j4*2+1] = fma2(hk2, w.y, acc[j4*2+1]);
            }
        }
        #pragma unroll
        for (int j2 = 0; j2 < 16; j2++) {
            float lo, hi; unpack2(acc[j2], lo, hi);
            s2 += lo + hi;
            sq2 = fmaf(lo, lo, fmaf(hi, hi, sq2));
            sx[tid * 33 + j2*2]     = lo;   // own row: no sync needed
            sx[tid * 33 + j2*2 + 1] = hi;
        }
    }

    // half B: j = 32..63 -> kept in regs
    float hb[32];
    {
        unsigned long long acc[16];
        #pragma unroll
        for (int j2 = 0; j2 < 16; j2++)
            acc[j2] = reinterpret_cast<const unsigned long long*>(sb2)[16 + j2];

        #pragma unroll 8
        for (int k = 0; k < H; k++) {
            unsigned long long hk2 = pack2(h1[k]);
            const ulonglong2* wrow = reinterpret_cast<const ulonglong2*>(&sW2[k * H + 32]);
            #pragma unroll
            for (int j4 = 0; j4 < 8; j4++) {
                ulonglong2 w = wrow[j4];
                acc[j4*2+0] = fma2(hk2, w.x, acc[j4*2+0]);
                acc[j4*2+1] = fma2(hk2, w.y, acc[j4*2+1]);
            }
        }
        #pragma unroll
        for (int j2 = 0; j2 < 16; j2++) {
            unpack2(acc[j2], hb[j2*2], hb[j2*2+1]);
            s2 += hb[j2*2] + hb[j2*2+1];
            sq2 = fmaf(hb[j2*2], hb[j2*2], fmaf(hb[j2*2+1], hb[j2*2+1], sq2));
        }
    }

    float mu  = s2 * (1.f / H);
    float var = sq2 * (1.f / H) - mu * mu;
    float inv = rsqrtf(var + EPS);

    // finalize half A in staging (LN + ReLU, own row)
    #pragma unroll
    for (int c = 0; c < 32; c++) {
        float v = sx[tid * 33 + c];
        sx[tid * 33 + c] = fmaxf(fmaf((v - mu) * inv, sg2[c], sbe2[c]), 0.f);
    }
    __syncthreads();
    // transposed coalesced writeback: half A (features 0..31)
    for (int l = tid; l < 128 * 32; l += 128) {
        int n = l >> 5, j = l & 31;
        int node = B + n;
        if (node < N_NODES) {
            float v = sx[n * 33 + j];
            size_t o = (size_t)node * H + j;
            h_out[o] = v;
            out[o]   = v;
        }
    }
    __syncthreads();
    // stage half B (LN + ReLU applied in regs)
    #pragma unroll
    for (int c = 0; c < 32; c++)
        sx[tid * 33 + c] = fmaxf(fmaf((hb[c] - mu) * inv, sg2[32 + c], sbe2[32 + c]), 0.f);
    __syncthreads();
    for (int l = tid; l < 128 * 32; l += 128) {
        int n = l >> 5, j = l & 31;
        int node = B + n;
        if (node < N_NODES) {
            float v = sx[n * 33 + j];
            size_t o = (size_t)node * H + 32 + j;
            h_out[o] = v;
            out[o]   = v;
        }
    }
}

// ---------------------------------------------------------------------------
// Edge scatter: out[row] += h[col]. 16 threads/edge, red.global.add.v4.f32.
// At the LDG/REDG issue floor (3 rounds of identical counters) — do not touch.
// ---------------------------------------------------------------------------
__global__ __launch_bounds__(256)
void edge_kernel(const int* __restrict__ ei,
                 const float4* __restrict__ h4,
                 float* __restrict__ out)
{
    long long idx = (long long)blockIdx.x * blockDim.x + threadIdx.x;
    int  lane16 = (int)(idx & 15);
    long long e = idx >> 4;
    if (e >= N_EDGES) return;

    int row = ei[e];            // destination
    int col = ei[N_EDGES + e];  // source
    if ((unsigned)row >= N_NODES || (unsigned)col >= N_NODES) return;

    float4 v = h4[(long long)col * 16 + lane16];
    float* p = out + (long long)row * H + lane16 * 4;
    asm volatile("red.global.add.v4.f32 [%0], {%1,%2,%3,%4};"
                 :: "l"(p), "f"(v.x), "f"(v.y), "f"(v.z), "f"(v.w)
                 : "memory");
}

// ---------------------------------------------------------------------------
extern "C" void kernel_launch(void* const* d_in, const int* in_sizes, int n_in,
                              void* d_out, int out_size)
{
    const float* x   = (const float*)d_in[0];
    const int*   ei  = (const int*)d_in[1];
    const float* W1  = (const float*)d_in[2];
    const float* b1  = (const float*)d_in[3];
    const float* g1  = (const float*)d_in[4];
    const float* be1 = (const float*)d_in[5];
    const float* W2  = (const float*)d_in[6];
    const float* b2  = (const float*)d_in[7];
    const float* g2  = (const float*)d_in[8];
    const float* be2 = (const float*)d_in[9];
    float* out = (float*)d_out;

    float* h_buf;
    cudaGetSymbolAddress((void**)&h_buf, g_h);

    mlp_kernel<<<(N_NODES + 127) / 128, 128>>>(x, W1, b1, g1, be1,
                                               W2, b2, g2, be2, h_buf, out);

    long long total = (long long)N_EDGES * 16;
    int blocks = (int)((total + 255) / 256);
    edge_kernel<<<blocks, 256>>>(ei, (const float4*)h_buf, out);
}

// round 9
// speedup vs baseline: 1.1304x; 1.1304x over previous
#include <cuda_runtime.h>
#include <cuda_bf16.h>
#include <cstdint>

#define N_NODES 100000
#define N_EDGES 1250000
#define D_IN 32
#define H 64
#define EPS 1e-5f
#define EPT 4                       // edges per thread in edge kernel
#define NQ (N_EDGES / EPT)          // 312500 (exact)

// scratch for hidden features h [N_NODES, H]
__device__ float g_h[(size_t)N_NODES * H];

// packed f32x2 helpers (Blackwell FFMA2 — only reachable via PTX)
__device__ __forceinline__ unsigned long long fma2(unsigned long long a,
                                                   unsigned long long b,
                                                   unsigned long long c)
{
    unsigned long long d;
    asm("fma.rn.f32x2 %0, %1, %2, %3;" : "=l"(d) : "l"(a), "l"(b), "l"(c));
    return d;
}
__device__ __forceinline__ unsigned long long pack2(float v)
{
    unsigned long long d;
    unsigned int u = __float_as_uint(v);
    asm("mov.b64 %0, {%1, %1};" : "=l"(d) : "r"(u));
    return d;
}
__device__ __forceinline__ void unpack2(unsigned long long v, float& lo, float& hi)
{
    unsigned int a, b;
    asm("mov.b64 {%0, %1}, %2;" : "=r"(a), "=r"(b) : "l"(v));
    lo = __uint_as_float(a); hi = __uint_as_float(b);
}

// ---------------------------------------------------------------------------
// MLP (R6 version — best measured): thread = node, packed f32x2 accumulators,
// broadcast LDS.128 weights, conflict-free smem x (stride 33), 4 blocks/SM.
// Writes h to g_h AND initializes out = h.
// ---------------------------------------------------------------------------
__global__ __launch_bounds__(128, 4)
void mlp_kernel(const float* __restrict__ x,
                const float* __restrict__ W1, const float* __restrict__ b1,
                const float* __restrict__ g1, const float* __restrict__ be1,
                const float* __restrict__ W2, const float* __restrict__ b2,
                const float* __restrict__ g2, const float* __restrict__ be2,
                float* __restrict__ h_out, float* __restrict__ out)
{
    __shared__ __align__(16) float sW1[D_IN * H];
    __shared__ __align__(16) float sW2[H * H];
    __shared__ __align__(16) float sx[128 * 33];
    __shared__ __align__(16) float sb1[H], sg1[H], sbe1[H], sb2[H], sg2[H], sbe2[H];

    const int tid = threadIdx.x;
    const int B   = blockIdx.x * 128;

    for (int i = tid; i < D_IN * H; i += 128) sW1[i] = W1[i];
    for (int i = tid; i < H * H;    i += 128) sW2[i] = W2[i];
    if (tid < H) {
        sb1[tid] = b1[tid]; sg1[tid] = g1[tid]; sbe1[tid] = be1[tid];
        sb2[tid] = b2[tid]; sg2[tid] = g2[tid]; sbe2[tid] = be2[tid];
    }

    for (int l = tid; l < 128 * D_IN; l += 128) {
        int n = l >> 5, k = l & 31;
        long long gidx = (long long)B * D_IN + l;
        sx[n * 33 + k] = (gidx < (long long)N_NODES * D_IN) ? x[gidx] : 0.f;
    }
    __syncthreads();

    // ---- layer 1: 32 -> 64 ----
    unsigned long long acc[H / 2];
    #pragma unroll
    for (int j2 = 0; j2 < H / 2; j2++)
        acc[j2] = reinterpret_cast<const unsigned long long*>(sb1)[j2];

    #pragma unroll 8
    for (int k = 0; k < D_IN; k++) {
        unsigned long long xk2 = pack2(sx[tid * 33 + k]);
        const ulonglong2* wrow = reinterpret_cast<const ulonglong2*>(&sW1[k * H]);
        #pragma unroll
        for (int j4 = 0; j4 < 16; j4++) {
            ulonglong2 w = wrow[j4];
            acc[j4*2+0] = fma2(xk2, w.x, acc[j4*2+0]);
            acc[j4*2+1] = fma2(xk2, w.y, acc[j4*2+1]);
        }
    }

    float h1[H];
    #pragma unroll
    for (int j2 = 0; j2 < H / 2; j2++) unpack2(acc[j2], h1[j2*2], h1[j2*2+1]);
    {
        float s = 0.f, sq = 0.f;
        #pragma unroll
        for (int j = 0; j < H; j++) { s += h1[j]; sq = fmaf(h1[j], h1[j], sq); }
        float mu  = s * (1.f / H);
        float var = sq * (1.f / H) - mu * mu;
        float inv = rsqrtf(var + EPS);
        #pragma unroll
        for (int j = 0; j < H; j++)
            h1[j] = fmaxf(fmaf((h1[j] - mu) * inv, sg1[j], sbe1[j]), 0.f);
    }

    // ---- layer 2: 64 -> 64 ----
    #pragma unroll
    for (int j2 = 0; j2 < H / 2; j2++)
        acc[j2] = reinterpret_cast<const unsigned long long*>(sb2)[j2];

    #pragma unroll 8
    for (int k = 0; k < H; k++) {
        unsigned long long hk2 = pack2(h1[k]);
        const ulonglong2* wrow = reinterpret_cast<const ulonglong2*>(&sW2[k * H]);
        #pragma unroll
        for (int j4 = 0; j4 < 16; j4++) {
            ulonglong2 w = wrow[j4];
            acc[j4*2+0] = fma2(hk2, w.x, acc[j4*2+0]);
            acc[j4*2+1] = fma2(hk2, w.y, acc[j4*2+1]);
        }
    }

    float h2[H];
    #pragma unroll
    for (int j2 = 0; j2 < H / 2; j2++) unpack2(acc[j2], h2[j2*2], h2[j2*2+1]);
    {
        float s = 0.f, sq = 0.f;
        #pragma unroll
        for (int j = 0; j < H; j++) { s += h2[j]; sq = fmaf(h2[j], h2[j], sq); }
        float mu  = s * (1.f / H);
        float var = sq * (1.f / H) - mu * mu;
        float inv = rsqrtf(var + EPS);
        #pragma unroll
        for (int j = 0; j < H; j++)
            h2[j] = fmaxf(fmaf((h2[j] - mu) * inv, sg2[j], sbe2[j]), 0.f);
    }

    // writeback via smem transpose (stride 33), two halves, coalesced STG
    #pragma unroll
    for (int half = 0; half < 2; half++) {
        __syncthreads();
        #pragma unroll
        for (int c = 0; c < 32; c++)
            sx[tid * 33 + c] = h2[half * 32 + c];
        __syncthreads();
        for (int l = tid; l < 128 * 32; l += 128) {
            int n = l >> 5, j = l & 31;
            int node = B + n;
            if (node < N_NODES) {
                float v = sx[n * 33 + j];
                size_t o = (size_t)node * H + half * 32 + j;
                h_out[o] = v;
                out[o]   = v;
            }
        }
    }
}

// ---------------------------------------------------------------------------
// Edge scatter: out[row] += h[col]. 16 threads per edge-slice, 4 edges per
// thread (strided by NQ) -> 4 independent LDG->RED chains per thread for
// memory-level parallelism. red.global.add.v4.f32 (no-return).
// ---------------------------------------------------------------------------
__global__ __launch_bounds__(256)
void edge_kernel(const int* __restrict__ ei,
                 const float4* __restrict__ h4,
                 float* __restrict__ out)
{
    long long idx = (long long)blockIdx.x * blockDim.x + threadIdx.x;
    int f = (int)(idx & 15);            // float4 slice 0..15
    long long e0 = idx >> 4;
    if (e0 >= NQ) return;

    int rows[EPT], cols[EPT];
    #pragma unroll
    for (int j = 0; j < EPT; j++) {
        long long e = e0 + (long long)j * NQ;
        rows[j] = ei[e];
        cols[j] = ei[N_EDGES + e];
    }

    float4 v[EPT];
    #pragma unroll
    for (int j = 0; j < EPT; j++) {
        int c = ((unsigned)cols[j] < N_NODES) ? cols[j] : 0;
        v[j] = h4[(long long)c * 16 + f];
    }

    #pragma unroll
    for (int j = 0; j < EPT; j++) {
        if ((unsigned)rows[j] >= N_NODES || (unsigned)cols[j] >= N_NODES) continue;
        float* p = out + (long long)rows[j] * H + f * 4;
        asm volatile("red.global.add.v4.f32 [%0], {%1,%2,%3,%4};"
                     :: "l"(p), "f"(v[j].x), "f"(v[j].y), "f"(v[j].z), "f"(v[j].w)
                     : "memory");
    }
}

// ---------------------------------------------------------------------------
extern "C" void kernel_launch(void* const* d_in, const int* in_sizes, int n_in,
                              void* d_out, int out_size)
{
    const float* x   = (const float*)d_in[0];
    const int*   ei  = (const int*)d_in[1];
    const float* W1  = (const float*)d_in[2];
    const float* b1  = (const float*)d_in[3];
    const float* g1  = (const float*)d_in[4];
    const float* be1 = (const float*)d_in[5];
    const float* W2  = (const float*)d_in[6];
    const float* b2  = (const float*)d_in[7];
    const float* g2  = (const float*)d_in[8];
    const float* be2 = (const float*)d_in[9];
    float* out = (float*)d_out;

    float* h_buf;
    cudaGetSymbolAddress((void**)&h_buf, g_h);

    mlp_kernel<<<(N_NODES + 127) / 128, 128>>>(x, W1, b1, g1, be1,
                                               W2, b2, g2, be2, h_buf, out);

    long long total = (long long)NQ * 16;
    int blocks = (int)((total + 255) / 256);
    edge_kernel<<<blocks, 256>>>(ei, (const float4*)h_buf, out);
}

// round 12
// speedup vs baseline: 1.1468x; 1.0145x over previous
#include <cuda_runtime.h>
#include <cuda_bf16.h>
#include <cstdint>

#define N_NODES 100000
#define N_EDGES 1250000
#define D_IN 32
#define H 64
#define EPS 1e-5f
#define EPT 8                       // edges per thread in edge kernel
#define NQ (N_EDGES / EPT)          // 156250 (exact)

// scratch for hidden features h [N_NODES, H]
__device__ float g_h[(size_t)N_NODES * H];

// packed f32x2 helpers (Blackwell FFMA2 — only reachable via PTX)
__device__ __forceinline__ unsigned long long fma2(unsigned long long a,
                                                   unsigned long long b,
                                                   unsigned long long c)
{
    unsigned long long d;
    asm("fma.rn.f32x2 %0, %1, %2, %3;" : "=l"(d) : "l"(a), "l"(b), "l"(c));
    return d;
}
__device__ __forceinline__ unsigned long long pack2(float v)
{
    unsigned long long d;
    unsigned int u = __float_as_uint(v);
    asm("mov.b64 %0, {%1, %1};" : "=l"(d) : "r"(u));
    return d;
}
__device__ __forceinline__ void unpack2(unsigned long long v, float& lo, float& hi)
{
    unsigned int a, b;
    asm("mov.b64 {%0, %1}, %2;" : "=r"(a), "=r"(b) : "l"(v));
    lo = __uint_as_float(a); hi = __uint_as_float(b);
}

#define NPB 128          // nodes per block
#define BSTR 67          // buf row stride (odd -> all banks hit)

// ---------------------------------------------------------------------------
// MLP: 2 threads per node (one per 32-output half), halves assigned per-WARP
// so weight LDS.128 is warp-broadcast. 16 b64 accumulators/thread -> ~70 live
// regs -> 24 warps/SM (3 blocks x 256).
// RACE FIX vs R10: layer-1 results stay in registers until AFTER the
// __syncthreads() that proves all x reads are done; only then written to buf.
// ---------------------------------------------------------------------------
__global__ __launch_bounds__(256, 3)
void mlp_kernel(const float* __restrict__ x,
                const float* __restrict__ W1, const float* __restrict__ b1,
                const float* __restrict__ g1, const float* __restrict__ be1,
                const float* __restrict__ W2, const float* __restrict__ b2,
                const float* __restrict__ g2, const float* __restrict__ be2,
                float* __restrict__ h_out, float* __restrict__ out)
{
    __shared__ __align__(16) float sW1[D_IN * H];      // 8 KB
    __shared__ __align__(16) float sW2[H * H];         // 16 KB
    __shared__ __align__(16) float buf[NPB * BSTR];    // 34.3 KB
    __shared__ float sred[NPB][2][2];                  // 2 KB  [node][half][s,sq]
    __shared__ __align__(16) float sb1[H], sg1[H], sbe1[H], sb2[H], sg2[H], sbe2[H];

    const int tid  = threadIdx.x;
    const int wid  = tid >> 5;
    const int lane = tid & 31;
    const int half = wid & 1;                  // warp-uniform half
    const int node = (wid >> 1) * 32 + lane;   // 0..127 local node
    const int B    = blockIdx.x * NPB;

    for (int i = tid; i < D_IN * H; i += 256) sW1[i] = W1[i];
    for (int i = tid; i < H * H;    i += 256) sW2[i] = W2[i];
    if (tid < H) {
        sb1[tid] = b1[tid]; sg1[tid] = g1[tid]; sbe1[tid] = be1[tid];
        sb2[tid] = b2[tid]; sg2[tid] = g2[tid]; sbe2[tid] = be2[tid];
    }

    // stage x tile coalesced into buf (cols 0..31)
    for (int l = tid; l < NPB * D_IN; l += 256) {
        int n = l >> 5, k = l & 31;
        long long gidx = (long long)B * D_IN + l;
        buf[n * BSTR + k] = (gidx < (long long)N_NODES * D_IN) ? x[gidx] : 0.f;
    }
    __syncthreads();

    const float* myrow = &buf[node * BSTR];
    float*       myout = &buf[node * BSTR + half * 32];

    // ---- layer 1: 32 -> this thread's 32 outputs (kept in regs) ----
    float r[32];
    {
        unsigned long long acc[16];
        #pragma unroll
        for (int j2 = 0; j2 < 16; j2++)
            acc[j2] = reinterpret_cast<const unsigned long long*>(sb1)[half * 16 + j2];

        #pragma unroll 8
        for (int k = 0; k < D_IN; k++) {
            unsigned long long xk2 = pack2(myrow[k]);
            const ulonglong2* wrow =
                reinterpret_cast<const ulonglong2*>(&sW1[k * H + half * 32]);
            #pragma unroll
            for (int j4 = 0; j4 < 8; j4++) {
                ulonglong2 w = wrow[j4];
                acc[j4*2+0] = fma2(xk2, w.x, acc[j4*2+0]);
                acc[j4*2+1] = fma2(xk2, w.y, acc[j4*2+1]);
            }
        }
        float s = 0.f, sq = 0.f;
        #pragma unroll
        for (int j2 = 0; j2 < 16; j2++) {
            unpack2(acc[j2], r[j2*2], r[j2*2+1]);
            s += r[j2*2] + r[j2*2+1];
            sq = fmaf(r[j2*2], r[j2*2], fmaf(r[j2*2+1], r[j2*2+1], sq));
        }
        sred[node][half][0] = s;
        sred[node][half][1] = sq;
    }
    __syncthreads();   // ALL x reads complete; sred visible

    // LN1 + ReLU from regs -> write h1 into buf (overwrites x, now safe)
    {
        float sum   = sred[node][0][0] + sred[node][1][0];
        float sumsq = sred[node][0][1] + sred[node][1][1];
        float mu  = sum * (1.f / H);
        float var = sumsq * (1.f / H) - mu * mu;
        float inv = rsqrtf(var + EPS);
        #pragma unroll
        for (int c = 0; c < 32; c++)
            myout[c] = fmaxf(fmaf((r[c] - mu) * inv, sg1[half*32 + c], sbe1[half*32 + c]), 0.f);
    }
    __syncthreads();   // h1 fully in buf

    // ---- layer 2: 64 -> this thread's 32 outputs ----
    {
        unsigned long long acc[16];
        #pragma unroll
        for (int j2 = 0; j2 < 16; j2++)
            acc[j2] = reinterpret_cast<const unsigned long long*>(sb2)[half * 16 + j2];

        #pragma unroll 8
        for (int k = 0; k < H; k++) {
            unsigned long long hk2 = pack2(myrow[k]);
            const ulonglong2* wrow =
                reinterpret_cast<const ulonglong2*>(&sW2[k * H + half * 32]);
            #pragma unroll
            for (int j4 = 0; j4 < 8; j4++) {
                ulonglong2 w = wrow[j4];
                acc[j4*2+0] = fma2(hk2, w.x, acc[j4*2+0]);
                acc[j4*2+1] = fma2(hk2, w.y, acc[j4*2+1]);
            }
        }
        float s = 0.f, sq = 0.f;
        #pragma unroll
        for (int j2 = 0; j2 < 16; j2++) {
            unpack2(acc[j2], r[j2*2], r[j2*2+1]);
            s += r[j2*2] + r[j2*2+1];
            sq = fmaf(r[j2*2], r[j2*2], fmaf(r[j2*2+1], r[j2*2+1], sq));
        }
        sred[node][half][0] = s;
        sred[node][half][1] = sq;
    }
    __syncthreads();   // ALL h1 reads complete; sred visible

    {
        float sum   = sred[node][0][0] + sred[node][1][0];
        float sumsq = sred[node][0][1] + sred[node][1][1];
        float mu  = sum * (1.f / H);
        float var = sumsq * (1.f / H) - mu * mu;
        float inv = rsqrtf(var + EPS);
        #pragma unroll
        for (int c = 0; c < 32; c++)
            myout[c] = fmaxf(fmaf((r[c] - mu) * inv, sg2[half*32 + c], sbe2[half*32 + c]), 0.f);
    }
    __syncthreads();   // h2 fully in buf

    // coalesced writeback: h_out and out = h
    for (int l = tid; l < NPB * H; l += 256) {
        int n = l >> 6, j = l & 63;
        int gn = B + n;
        if (gn < N_NODES) {
            float v = buf[n * BSTR + j];
            size_t o = (size_t)gn * H + j;
            h_out[o] = v;
            out[o]   = v;
        }
    }
}

// ---------------------------------------------------------------------------
// Edge scatter: out[row] += h[col]. 16 threads per edge-slice, 8 edges per
// thread (strided by NQ) -> 8 independent LDG->RED chains per thread.
// ---------------------------------------------------------------------------
__global__ __launch_bounds__(256)
void edge_kernel(const int* __restrict__ ei,
                 const float4* __restrict__ h4,
                 float* __restrict__ out)
{
    long long idx = (long long)blockIdx.x * blockDim.x + threadIdx.x;
    int f = (int)(idx & 15);            // float4 slice 0..15
    long long e0 = idx >> 4;
    if (e0 >= NQ) return;

    int rows[EPT], cols[EPT];
    #pragma unroll
    for (int j = 0; j < EPT; j++) {
        long long e = e0 + (long long)j * NQ;
        rows[j] = ei[e];
        cols[j] = ei[N_EDGES + e];
    }

    float4 v[EPT];
    #pragma unroll
    for (int j = 0; j < EPT; j++) {
        int c = ((unsigned)cols[j] < N_NODES) ? cols[j] : 0;
        v[j] = h4[(long long)c * 16 + f];
    }

    #pragma unroll
    for (int j = 0; j < EPT; j++) {
        if ((unsigned)rows[j] >= N_NODES || (unsigned)cols[j] >= N_NODES) continue;
        float* p = out + (long long)rows[j] * H + f * 4;
        asm volatile("red.global.add.v4.f32 [%0], {%1,%2,%3,%4};"
                     :: "l"(p), "f"(v[j].x), "f"(v[j].y), "f"(v[j].z), "f"(v[j].w)
                     : "memory");
    }
}

// ---------------------------------------------------------------------------
extern "C" void kernel_launch(void* const* d_in, const int* in_sizes, int n_in,
                              void* d_out, int out_size)
{
    const float* x   = (const float*)d_in[0];
    const int*   ei  = (const int*)d_in[1];
    const float* W1  = (const float*)d_in[2];
    const float* b1  = (const float*)d_in[3];
    const float* g1  = (const float*)d_in[4];
    const float* be1 = (const float*)d_in[5];
    const float* W2  = (const float*)d_in[6];
    const float* b2  = (const float*)d_in[7];
    const float* g2  = (const float*)d_in[8];
    const float* be2 = (const float*)d_in[9];
    float* out = (float*)d_out;

    float* h_buf;
    cudaGetSymbolAddress((void**)&h_buf, g_h);

    mlp_kernel<<<(N_NODES + NPB - 1) / NPB, 256>>>(x, W1, b1, g1, be1,
                                                   W2, b2, g2, be2, h_buf, out);

    long long total = (long long)NQ * 16;
    int blocks = (int)((total + 255) / 256);
    edge_kernel<<<blocks, 256>>>(ei, (const float4*)h_buf, out);
}

// round 13
// speedup vs baseline: 1.2374x; 1.0791x over previous
#include <cuda_runtime.h>
#include <cuda_bf16.h>
#include <cstdint>

#define N_NODES 100000
#define N_EDGES 1250000
#define D_IN 32
#define H 64
#define EPS 1e-5f
#define EPT 4                       // edges per thread (R9 measured best)
#define NQ (N_EDGES / EPT)          // 312500 (exact)

// scratch for hidden features h [N_NODES, H]
__device__ float g_h[(size_t)N_NODES * H];

// packed f32x2 helpers (Blackwell FFMA2 — only reachable via PTX)
__device__ __forceinline__ unsigned long long fma2(unsigned long long a,
                                                   unsigned long long b,
                                                   unsigned long long c)
{
    unsigned long long d;
    asm("fma.rn.f32x2 %0, %1, %2, %3;" : "=l"(d) : "l"(a), "l"(b), "l"(c));
    return d;
}
__device__ __forceinline__ unsigned long long pack2(float v)
{
    unsigned long long d;
    unsigned int u = __float_as_uint(v);
    asm("mov.b64 %0, {%1, %1};" : "=l"(d) : "r"(u));
    return d;
}
__device__ __forceinline__ void unpack2(unsigned long long v, float& lo, float& hi)
{
    unsigned int a, b;
    asm("mov.b64 {%0, %1}, %2;" : "=r"(a), "=r"(b) : "l"(v));
    lo = __uint_as_float(a); hi = __uint_as_float(b);
}

#define NPB 64           // nodes per block
#define BSTR 67          // buf row stride (odd -> conflict-free scalar access)

// ---------------------------------------------------------------------------
// MLP: 4 threads per node (one per 16-output quarter), quarter assigned
// per-WARP so weight LDS.128 is warp-broadcast. 8 b64 accumulators/thread
// -> ~45 live regs; smem ~44 KB -> 5 blocks/SM = 40 warps/SM.
// ---------------------------------------------------------------------------
__global__ __launch_bounds__(256, 5)
void mlp_kernel(const float* __restrict__ x,
                const float* __restrict__ W1, const float* __restrict__ b1,
                const float* __restrict__ g1, const float* __restrict__ be1,
                const float* __restrict__ W2, const float* __restrict__ b2,
                const float* __restrict__ g2, const float* __restrict__ be2,
                float* __restrict__ h_out, float* __restrict__ out)
{
    __shared__ __align__(16) float sW1[D_IN * H];      // 8 KB
    __shared__ __align__(16) float sW2[H * H];         // 16 KB
    __shared__ __align__(16) float buf[NPB * BSTR];    // 17.2 KB
    __shared__ float sred[NPB][4][2];                  // 2 KB [node][quarter][s,sq]
    __shared__ __align__(16) float sb1[H], sg1[H], sbe1[H], sb2[H], sg2[H], sbe2[H];

    const int tid  = threadIdx.x;
    const int wid  = tid >> 5;
    const int lane = tid & 31;
    const int q    = wid & 3;                  // warp-uniform quarter (0..3)
    const int node = (wid >> 2) * 32 + lane;   // 0..63 local node
    const int B    = blockIdx.x * NPB;

    for (int i = tid; i < D_IN * H; i += 256) sW1[i] = W1[i];
    for (int i = tid; i < H * H;    i += 256) sW2[i] = W2[i];
    if (tid < H) {
        sb1[tid] = b1[tid]; sg1[tid] = g1[tid]; sbe1[tid] = be1[tid];
        sb2[tid] = b2[tid]; sg2[tid] = g2[tid]; sbe2[tid] = be2[tid];
    }

    // stage x tile coalesced into buf (cols 0..31)
    for (int l = tid; l < NPB * D_IN; l += 256) {
        int n = l >> 5, k = l & 31;
        long long gidx = (long long)B * D_IN + l;
        buf[n * BSTR + k] = (gidx < (long long)N_NODES * D_IN) ? x[gidx] : 0.f;
    }
    __syncthreads();

    const float* myrow = &buf[node * BSTR];
    float*       myout = &buf[node * BSTR + q * 16];

    // ---- layer 1: 32 -> this thread's 16 outputs (kept in regs) ----
    float r[16];
    {
        unsigned long long acc[8];
        #pragma unroll
        for (int j2 = 0; j2 < 8; j2++)
            acc[j2] = reinterpret_cast<const unsigned long long*>(sb1)[q * 8 + j2];

        #pragma unroll 8
        for (int k = 0; k < D_IN; k++) {
            unsigned long long xk2 = pack2(myrow[k]);
            const ulonglong2* wrow =
                reinterpret_cast<const ulonglong2*>(&sW1[k * H + q * 16]);
            #pragma unroll
            for (int j4 = 0; j4 < 4; j4++) {
                ulonglong2 w = wrow[j4];
                acc[j4*2+0] = fma2(xk2, w.x, acc[j4*2+0]);
                acc[j4*2+1] = fma2(xk2, w.y, acc[j4*2+1]);
            }
        }
        float s = 0.f, sq = 0.f;
        #pragma unroll
        for (int j2 = 0; j2 < 8; j2++) {
            unpack2(acc[j2], r[j2*2], r[j2*2+1]);
            s += r[j2*2] + r[j2*2+1];
            sq = fmaf(r[j2*2], r[j2*2], fmaf(r[j2*2+1], r[j2*2+1], sq));
        }
        sred[node][q][0] = s;
        sred[node][q][1] = sq;
    }
    __syncthreads();   // all x reads complete; sred visible

    // LN1 + ReLU from regs -> write h1 into buf (overwrites x, now safe)
    {
        float sum   = sred[node][0][0] + sred[node][1][0]
                    + sred[node][2][0] + sred[node][3][0];
        float sumsq = sred[node][0][1] + sred[node][1][1]
                    + sred[node][2][1] + sred[node][3][1];
        float mu  = sum * (1.f / H);
        float var = sumsq * (1.f / H) - mu * mu;
        float inv = rsqrtf(var + EPS);
        #pragma unroll
        for (int c = 0; c < 16; c++)
            myout[c] = fmaxf(fmaf((r[c] - mu) * inv, sg1[q*16 + c], sbe1[q*16 + c]), 0.f);
    }
    __syncthreads();   // h1 fully in buf

    // ---- layer 2: 64 -> this thread's 16 outputs ----
    {
        unsigned long long acc[8];
        #pragma unroll
        for (int j2 = 0; j2 < 8; j2++)
            acc[j2] = reinterpret_cast<const unsigned long long*>(sb2)[q * 8 + j2];

        #pragma unroll 8
        for (int k = 0; k < H; k++) {
            unsigned long long hk2 = pack2(myrow[k]);
            const ulonglong2* wrow =
                reinterpret_cast<const ulonglong2*>(&sW2[k * H + q * 16]);
            #pragma unroll
            for (int j4 = 0; j4 < 4; j4++) {
                ulonglong2 w = wrow[j4];
                acc[j4*2+0] = fma2(hk2, w.x, acc[j4*2+0]);
                acc[j4*2+1] = fma2(hk2, w.y, acc[j4*2+1]);
            }
        }
        float s = 0.f, sq = 0.f;
        #pragma unroll
        for (int j2 = 0; j2 < 8; j2++) {
            unpack2(acc[j2], r[j2*2], r[j2*2+1]);
            s += r[j2*2] + r[j2*2+1];
            sq = fmaf(r[j2*2], r[j2*2], fmaf(r[j2*2+1], r[j2*2+1], sq));
        }
        sred[node][q][0] = s;
        sred[node][q][1] = sq;
    }
    __syncthreads();   // all h1 reads complete; sred visible

    {
        float sum   = sred[node][0][0] + sred[node][1][0]
                    + sred[node][2][0] + sred[node][3][0];
        float sumsq = sred[node][0][1] + sred[node][1][1]
                    + sred[node][2][1] + sred[node][3][1];
        float mu  = sum * (1.f / H);
        float var = sumsq * (1.f / H) - mu * mu;
        float inv = rsqrtf(var + EPS);
        #pragma unroll
        for (int c = 0; c < 16; c++)
            myout[c] = fmaxf(fmaf((r[c] - mu) * inv, sg2[q*16 + c], sbe2[q*16 + c]), 0.f);
    }
    __syncthreads();   // h2 fully in buf

    // coalesced writeback: h_out and out = h
    for (int l = tid; l < NPB * H; l += 256) {
        int n = l >> 6, j = l & 63;
        int gn = B + n;
        if (gn < N_NODES) {
            float v = buf[n * BSTR + j];
            size_t o = (size_t)gn * H + j;
            h_out[o] = v;
            out[o]   = v;
        }
    }
}

// ---------------------------------------------------------------------------
// Edge scatter (R9 version — measured best): 16 threads per edge-slice,
// 4 edges per thread (strided by NQ) -> 4 independent LDG->RED chains.
// ---------------------------------------------------------------------------
__global__ __launch_bounds__(256)
void edge_kernel(const int* __restrict__ ei,
                 const float4* __restrict__ h4,
                 float* __restrict__ out)
{
    long long idx = (long long)blockIdx.x * blockDim.x + threadIdx.x;
    int f = (int)(idx & 15);            // float4 slice 0..15
    long long e0 = idx >> 4;
    if (e0 >= NQ) return;

    int rows[EPT], cols[EPT];
    #pragma unroll
    for (int j = 0; j < EPT; j++) {
        long long e = e0 + (long long)j * NQ;
        rows[j] = ei[e];
        cols[j] = ei[N_EDGES + e];
    }

    float4 v[EPT];
    #pragma unroll
    for (int j = 0; j < EPT; j++) {
        int c = ((unsigned)cols[j] < N_NODES) ? cols[j] : 0;
        v[j] = h4[(long long)c * 16 + f];
    }

    #pragma unroll
    for (int j = 0; j < EPT; j++) {
        if ((unsigned)rows[j] >= N_NODES || (unsigned)cols[j] >= N_NODES) continue;
        float* p = out + (long long)rows[j] * H + f * 4;
        asm volatile("red.global.add.v4.f32 [%0], {%1,%2,%3,%4};"
                     :: "l"(p), "f"(v[j].x), "f"(v[j].y), "f"(v[j].z), "f"(v[j].w)
                     : "memory");
    }
}

// ---------------------------------------------------------------------------
extern "C" void kernel_launch(void* const* d_in, const int* in_sizes, int n_in,
                              void* d_out, int out_size)
{
    const float* x   = (const float*)d_in[0];
    const int*   ei  = (const int*)d_in[1];
    const float* W1  = (const float*)d_in[2];
    const float* b1  = (const float*)d_in[3];
    const float* g1  = (const float*)d_in[4];
    const float* be1 = (const float*)d_in[5];
    const float* W2  = (const float*)d_in[6];
    const float* b2  = (const float*)d_in[7];
    const float* g2  = (const float*)d_in[8];
    const float* be2 = (const float*)d_in[9];
    float* out = (float*)d_out;

    float* h_buf;
    cudaGetSymbolAddress((void**)&h_buf, g_h);

    mlp_kernel<<<(N_NODES + NPB - 1) / NPB, 256>>>(x, W1, b1, g1, be1,
                                                   W2, b2, g2, be2, h_buf, out);

    long long total = (long long)NQ * 16;
    int blocks = (int)((total + 255) / 256);
    edge_kernel<<<blocks, 256>>>(ei, (const float4*)h_buf, out);
}

// round 16
// speedup vs baseline: 1.2737x; 1.0293x over previous
#include <cuda_runtime.h>
#include <cuda_fp16.h>
#include <cstdint>

#define N_NODES 100000
#define N_EDGES 1250000
#define D_IN 32
#define H 64
#define EPS 1e-5f
#define EPT 4                       // edges per thread (R9/R13 measured best)
#define NQ (N_EDGES / EPT)          // 312500 (exact)

// scratch: hidden features h in fp16 [N_NODES, H] (gather operand only)
__device__ __half g_h16[(size_t)N_NODES * H];

// packed f32x2 helpers (Blackwell FFMA2 — only reachable via PTX)
__device__ __forceinline__ unsigned long long fma2(unsigned long long a,
                                                   unsigned long long b,
                                                   unsigned long long c)
{
    unsigned long long d;
    asm("fma.rn.f32x2 %0, %1, %2, %3;" : "=l"(d) : "l"(a), "l"(b), "l"(c));
    return d;
}
__device__ __forceinline__ unsigned long long pack2(float v)
{
    unsigned long long d;
    unsigned int u = __float_as_uint(v);
    asm("mov.b64 %0, {%1, %1};" : "=l"(d) : "r"(u));
    return d;
}
__device__ __forceinline__ void unpack2(unsigned long long v, float& lo, float& hi)
{
    unsigned int a, b;
    asm("mov.b64 {%0, %1}, %2;" : "=r"(a), "=r"(b) : "l"(v));
    lo = __uint_as_float(a); hi = __uint_as_float(b);
}

#define NPB 64           // nodes per block
#define BSTR 67          // buf row stride (odd -> conflict-free scalar access)

// ---------------------------------------------------------------------------
// MLP (R13 structure): 4 threads/node, quarter per warp, 8 b64 accumulators,
// 5 blocks/SM. Writes out = h (fp32) and g_h16 = h (fp16) for the gather.
// ---------------------------------------------------------------------------
__global__ __launch_bounds__(256, 5)
void mlp_kernel(const float* __restrict__ x,
                const float* __restrict__ W1, const float* __restrict__ b1,
                const float* __restrict__ g1, const float* __restrict__ be1,
                const float* __restrict__ W2, const float* __restrict__ b2,
                const float* __restrict__ g2, const float* __restrict__ be2,
                __half* __restrict__ h16_out, float* __restrict__ out)
{
    __shared__ __align__(16) float sW1[D_IN * H];      // 8 KB
    __shared__ __align__(16) float sW2[H * H];         // 16 KB
    __shared__ __align__(16) float buf[NPB * BSTR];    // 17.2 KB
    __shared__ float sred[NPB][4][2];                  // 2 KB [node][quarter][s,sq]
    __shared__ __align__(16) float sb1[H], sg1[H], sbe1[H], sb2[H], sg2[H], sbe2[H];

    const int tid  = threadIdx.x;
    const int wid  = tid >> 5;
    const int lane = tid & 31;
    const int q    = wid & 3;                  // warp-uniform quarter (0..3)
    const int node = (wid >> 2) * 32 + lane;   // 0..63 local node
    const int B    = blockIdx.x * NPB;

    for (int i = tid; i < D_IN * H; i += 256) sW1[i] = W1[i];
    for (int i = tid; i < H * H;    i += 256) sW2[i] = W2[i];
    if (tid < H) {
        sb1[tid] = b1[tid]; sg1[tid] = g1[tid]; sbe1[tid] = be1[tid];
        sb2[tid] = b2[tid]; sg2[tid] = g2[tid]; sbe2[tid] = be2[tid];
    }

    // stage x tile coalesced into buf (cols 0..31)
    for (int l = tid; l < NPB * D_IN; l += 256) {
        int n = l >> 5, k = l & 31;
        long long gidx = (long long)B * D_IN + l;
        buf[n * BSTR + k] = (gidx < (long long)N_NODES * D_IN) ? x[gidx] : 0.f;
    }
    __syncthreads();

    const float* myrow = &buf[node * BSTR];
    float*       myout = &buf[node * BSTR + q * 16];

    // ---- layer 1: 32 -> this thread's 16 outputs (kept in regs) ----
    float r[16];
    {
        unsigned long long acc[8];
        #pragma unroll
        for (int j2 = 0; j2 < 8; j2++)
            acc[j2] = reinterpret_cast<const unsigned long long*>(sb1)[q * 8 + j2];

        #pragma unroll 8
        for (int k = 0; k < D_IN; k++) {
            unsigned long long xk2 = pack2(myrow[k]);
            const ulonglong2* wrow =
                reinterpret_cast<const ulonglong2*>(&sW1[k * H + q * 16]);
            #pragma unroll
            for (int j4 = 0; j4 < 4; j4++) {
                ulonglong2 w = wrow[j4];
                acc[j4*2+0] = fma2(xk2, w.x, acc[j4*2+0]);
                acc[j4*2+1] = fma2(xk2, w.y, acc[j4*2+1]);
            }
        }
        float s = 0.f, sq = 0.f;
        #pragma unroll
        for (int j2 = 0; j2 < 8; j2++) {
            unpack2(acc[j2], r[j2*2], r[j2*2+1]);
            s += r[j2*2] + r[j2*2+1];
            sq = fmaf(r[j2*2], r[j2*2], fmaf(r[j2*2+1], r[j2*2+1], sq));
        }
        sred[node][q][0] = s;
        sred[node][q][1] = sq;
    }
    __syncthreads();   // all x reads complete; sred visible

    // LN1 + ReLU from regs -> write h1 into buf (overwrites x, now safe)
    {
        float sum   = sred[node][0][0] + sred[node][1][0]
                    + sred[node][2][0] + sred[node][3][0];
        float sumsq = sred[node][0][1] + sred[node][1][1]
                    + sred[node][2][1] + sred[node][3][1];
        float mu  = sum * (1.f / H);
        float var = sumsq * (1.f / H) - mu * mu;
        float inv = rsqrtf(var + EPS);
        #pragma unroll
        for (int c = 0; c < 16; c++)
            myout[c] = fmaxf(fmaf((r[c] - mu) * inv, sg1[q*16 + c], sbe1[q*16 + c]), 0.f);
    }
    __syncthreads();   // h1 fully in buf

    // ---- layer 2: 64 -> this thread's 16 outputs ----
    {
        unsigned long long acc[8];
        #pragma unroll
        for (int j2 = 0; j2 < 8; j2++)
            acc[j2] = reinterpret_cast<const unsigned long long*>(sb2)[q * 8 + j2];

        #pragma unroll 8
        for (int k = 0; k < H; k++) {
            unsigned long long hk2 = pack2(myrow[k]);
            const ulonglong2* wrow =
                reinterpret_cast<const ulonglong2*>(&sW2[k * H + q * 16]);
            #pragma unroll
            for (int j4 = 0; j4 < 4; j4++) {
                ulonglong2 w = wrow[j4];
                acc[j4*2+0] = fma2(hk2, w.x, acc[j4*2+0]);
                acc[j4*2+1] = fma2(hk2, w.y, acc[j4*2+1]);
            }
        }
        float s = 0.f, sq = 0.f;
        #pragma unroll
        for (int j2 = 0; j2 < 8; j2++) {
            unpack2(acc[j2], r[j2*2], r[j2*2+1]);
            s += r[j2*2] + r[j2*2+1];
            sq = fmaf(r[j2*2], r[j2*2], fmaf(r[j2*2+1], r[j2*2+1], sq));
        }
        sred[node][q][0] = s;
        sred[node][q][1] = sq;
    }
    __syncthreads();   // all h1 reads complete; sred visible

    {
        float sum   = sred[node][0][0] + sred[node][1][0]
                    + sred[node][2][0] + sred[node][3][0];
        float sumsq = sred[node][0][1] + sred[node][1][1]
                    + sred[node][2][1] + sred[node][3][1];
        float mu  = sum * (1.f / H);
        float var = sumsq * (1.f / H) - mu * mu;
        float inv = rsqrtf(var + EPS);
        #pragma unroll
        for (int c = 0; c < 16; c++)
            myout[c] = fmaxf(fmaf((r[c] - mu) * inv, sg2[q*16 + c], sbe2[q*16 + c]), 0.f);
    }
    __syncthreads();   // h2 fully in buf

    // coalesced writeback: out = h (fp32) and h16 = h (fp16)
    for (int l = tid; l < NPB * H; l += 256) {
        int n = l >> 6, j = l & 63;
        int gn = B + n;
        if (gn < N_NODES)
            out[(size_t)gn * H + j] = buf[n * BSTR + j];
    }
    // fp16: pack pairs -> half2, 32 half2 per node
    for (int l = tid; l < NPB * (H / 2); l += 256) {
        int n = l >> 5, j = l & 31;          // j = half2 index 0..31
        int gn = B + n;
        if (gn < N_NODES) {
            float2 v = make_float2(buf[n * BSTR + 2*j], buf[n * BSTR + 2*j + 1]);
            reinterpret_cast<__half2*>(h16_out)[(size_t)gn * (H/2) + j] =
                __float22half2_rn(v);
        }
    }
}

// ---------------------------------------------------------------------------
// Edge scatter: out[row] += h16[col] (converted). 16 lanes/edge, each loads
// uint2 = 4 halves (128B per edge, coalesced), converts, issues red.v4.f32.
// EPT=4 independent chains per thread; ~28 regs keeps occupancy high.
// ---------------------------------------------------------------------------
__global__ __launch_bounds__(256)
void edge_kernel(const int* __restrict__ ei,
                 const uint2* __restrict__ h16,   // node row = 16 uint2
                 float* __restrict__ out)
{
    long long idx = (long long)blockIdx.x * blockDim.x + threadIdx.x;
    int f = (int)(idx & 15);            // 4-half slice 0..15
    long long e0 = idx >> 4;
    if (e0 >= NQ) return;

    int rows[EPT], cols[EPT];
    #pragma unroll
    for (int j = 0; j < EPT; j++) {
        long long e = e0 + (long long)j * NQ;
        rows[j] = ei[e];
        cols[j] = ei[N_EDGES + e];
    }

    uint2 v[EPT];
    #pragma unroll
    for (int j = 0; j < EPT; j++) {
        int c = ((unsigned)cols[j] < N_NODES) ? cols[j] : 0;
        v[j] = h16[(long long)c * 16 + f];
    }

    #pragma unroll
    for (int j = 0; j < EPT; j++) {
        if ((unsigned)rows[j] >= N_NODES || (unsigned)cols[j] >= N_NODES) continue;
        __half2 h0 = *reinterpret_cast<const __half2*>(&v[j].x);
        __half2 h1 = *reinterpret_cast<const __half2*>(&v[j].y);
        float2 f0 = __half22float2(h0);
        float2 f1 = __half22float2(h1);
        float* p = out + (long long)rows[j] * H + f * 4;
        asm volatile("red.global.add.v4.f32 [%0], {%1,%2,%3,%4};"
                     :: "l"(p), "f"(f0.x), "f"(f0.y), "f"(f1.x), "f"(f1.y)
                     : "memory");
    }
}

// ---------------------------------------------------------------------------
extern "C" void kernel_launch(void* const* d_in, const int* in_sizes, int n_in,
                              void* d_out, int out_size)
{
    const float* x   = (const float*)d_in[0];
    const int*   ei  = (const int*)d_in[1];
    const float* W1  = (const float*)d_in[2];
    const float* b1  = (const float*)d_in[3];
    const float* g1  = (const float*)d_in[4];
    const float* be1 = (const float*)d_in[5];
    const float* W2  = (const float*)d_in[6];
    const float* b2  = (const float*)d_in[7];
    const float* g2  = (const float*)d_in[8];
    const float* be2 = (const float*)d_in[9];
    float* out = (float*)d_out;

    __half* h16_buf;
    cudaGetSymbolAddress((void**)&h16_buf, g_h16);

    mlp_kernel<<<(N_NODES + NPB - 1) / NPB, 256>>>(x, W1, b1, g1, be1,
                                                   W2, b2, g2, be2, h16_buf, out);

    long long total = (long long)NQ * 16;
    int blocks = (int)((total + 255) / 256);
    edge_kernel<<<blocks, 256>>>(ei, (const uint2*)h16_buf, out);
}